// round 8
// baseline (speedup 1.0000x reference)
#include <cuda_runtime.h>
#include <cuda.h>
#include <cuda_bf16.h>
#include <cstdint>

// ---------------------------------------------------------------------------
// MemristiveLinear == y = x @ w + b (512^3 fp32), tcgen05 bf16 split:
//   x = xh+xl, w = wh+wl;  y ~= xh@wh + xh@wl + xl@wh  (+b)
//
// R8: canonical warp-specialized TMA pipeline (no generic-proxy writes,
//     no per-chunk fence.proxy.async, no per-chunk __syncthreads):
//   kernel 1: convert X->XH/XL [m][k], W->WTH/WTL [n][k] (bf16, validated R5)
//   kernel 2: 64 CTAs (M=128,N=32), 128 thr; 4-stage ring of K=64 chunks;
//             producer thread: TMA loads -> full[s] mbarrier
//             consumer thread: 12 MMA dispatches -> commit -> empty[s]
//   Tensor maps: built host-side per call via cudaGetDriverEntryPointByVersion
//   (capture-safe; no driver-lib link), passed __grid_constant__.
// tcgen05 asm guarded for the arch-specific pass; generic compute_103 pass
// compiles a correct fp32 fallback (never runs; sm_103a cubin preferred).
// ---------------------------------------------------------------------------

#if defined(__CUDA_ARCH_FEAT_SM103_ALL) || defined(__CUDA_ARCH_FEAT_SM100_ALL) || \
    defined(__CUDA_ARCH_FEAT_SM101_ALL) || defined(__CUDA_ARCH_SPECIFIC__) ||     \
    defined(__CUDA_ARCH_FAMILY_SPECIFIC__)
#define TC_OK 1
#else
#define TC_OK 0
#endif

#define MD 512
#define ND 512
#define KD 512

// bf16 scratch, stored as uint4 (8 bf16 each) for vector access.
__device__ uint4 gXH[MD * KD / 8];
__device__ uint4 gXL[MD * KD / 8];
__device__ uint4 gWTH[ND * KD / 8];
__device__ uint4 gWTL[ND * KD / 8];

// ---------------------------------------------------------------------------
// Convert kernel (validated in R5: produced passing results)
// ---------------------------------------------------------------------------
__device__ __forceinline__ void split_pair(float a, float b,
                                           unsigned& hp, unsigned& lp) {
    unsigned uha = __bfloat16_as_ushort(__float2bfloat16_rn(a));
    unsigned uhb = __bfloat16_as_ushort(__float2bfloat16_rn(b));
    float ra = a - __uint_as_float(uha << 16);
    float rb = b - __uint_as_float(uhb << 16);
    unsigned ula = __bfloat16_as_ushort(__float2bfloat16_rn(ra));
    unsigned ulb = __bfloat16_as_ushort(__float2bfloat16_rn(rb));
    hp = uha | (uhb << 16);
    lp = ula | (ulb << 16);
}

__global__ __launch_bounds__(256)
void convert_kernel(const float* __restrict__ X, const float* __restrict__ W) {
    __shared__ float sm[64][65];
    const int t = threadIdx.x;
    const int b = blockIdx.x;

    if (b < 64) {
        const float4* X4 = (const float4*)X;
        uint2* XH2 = (uint2*)gXH;
        uint2* XL2 = (uint2*)gXL;
#pragma unroll
        for (int j = 0; j < 4; j++) {
            const int f4 = b * 1024 + j * 256 + t;
            float4 v = X4[f4];
            unsigned h01, l01, h23, l23;
            split_pair(v.x, v.y, h01, l01);
            split_pair(v.z, v.w, h23, l23);
            XH2[f4] = make_uint2(h01, h23);
            XL2[f4] = make_uint2(l01, l23);
        }
    } else {
        const int bb = b - 64;
        const int tk = bb >> 3, tn = bb & 7;
        const int r = t >> 2, q4 = t & 3;
        const float* wrow = W + (tk * 64 + r) * ND + tn * 64;
#pragma unroll
        for (int j = 0; j < 4; j++) {
            float4 v = *(const float4*)(wrow + (q4 * 4 + j) * 4);
            sm[r][(q4 * 4 + j) * 4 + 0] = v.x;
            sm[r][(q4 * 4 + j) * 4 + 1] = v.y;
            sm[r][(q4 * 4 + j) * 4 + 2] = v.z;
            sm[r][(q4 * 4 + j) * 4 + 3] = v.w;
        }
        __syncthreads();
        const int c = t >> 2, qr = t & 3;
        uint2* WH2 = (uint2*)gWTH;
        uint2* WL2 = (uint2*)gWTL;
        const int outbase = ((tn * 64 + c) * KD + tk * 64 + qr * 16) / 4;
#pragma unroll
        for (int g = 0; g < 4; g++) {
            float v0 = sm[qr * 16 + 4 * g + 0][c];
            float v1 = sm[qr * 16 + 4 * g + 1][c];
            float v2 = sm[qr * 16 + 4 * g + 2][c];
            float v3 = sm[qr * 16 + 4 * g + 3][c];
            unsigned h01, l01, h23, l23;
            split_pair(v0, v1, h01, l01);
            split_pair(v2, v3, h23, l23);
            WH2[outbase + g] = make_uint2(h01, h23);
            WL2[outbase + g] = make_uint2(l01, l23);
        }
    }
}

// ---------------------------------------------------------------------------
// GEMM kernel
// ---------------------------------------------------------------------------
#define DESC_BASE 0x4000404000010000ull
#define MK_DESC(addr) (DESC_BASE | (((unsigned long long)((addr) >> 4)) & 0x3FFF))
// kind::f16 idesc: F32 acc, BF16 a/b, M=128, N=32 (validated R5-R7)
#define IDESC ((1u << 4) | (1u << 7) | (1u << 10) | (4u << 17) | (8u << 24))

// smem map (relative to 1024-aligned base):
//   0: tmem ptr | 8+8s: full[4] | 48+8s: empty[4]
//   stage s (s=0..3) at 1024 + s*40960: Ah 16K | Al 16K | Wh 4K | Wl 4K
#define STAGE0 1024
#define STAGE_STRIDE 40960
#define CHUNK_BYTES 40960
#define SMEM_DYN (STAGE0 + 4 * STAGE_STRIDE + 1024)  // 165888

__device__ __forceinline__ uint32_t s2u(const void* p) {
    uint32_t a;
    asm("{ .reg .u64 t; cvta.to.shared.u64 t, %1; cvt.u32.u64 %0, t; }"
        : "=r"(a) : "l"(p));
    return a;
}

#if TC_OK
__device__ __forceinline__ void mma_f16_ss(uint32_t d, unsigned long long ad,
                                           unsigned long long bd,
                                           uint32_t idesc, uint32_t en) {
    asm volatile(
        "{\n\t.reg .pred p;\n\tsetp.ne.u32 p, %5, 0;\n\t"
        "tcgen05.mma.cta_group::1.kind::f16 [%0], %1, %2, %3, {%4, %4, %4, %4}, p;\n\t}"
        :: "r"(d), "l"(ad), "l"(bd), "r"(idesc), "r"(0u), "r"(en)
        : "memory");
}

#define MBAR_INIT(a) \
    asm volatile("mbarrier.init.shared.b64 [%0], %1;" :: "r"(a), "r"(1u) : "memory")

#define MBAR_EXPECT_TX(a, n) \
    asm volatile("mbarrier.arrive.expect_tx.shared.b64 _, [%0], %1;" \
                 :: "r"(a), "r"(n) : "memory")

#define MBAR_WAITP(a, ph) do {                                                \
    unsigned _m = (a), _p = (ph), _d;                                         \
    asm volatile("{\n\t.reg .pred p;\n\t"                                     \
        "mbarrier.try_wait.parity.acquire.cta.shared::cta.b64 p, [%1], %2;\n\t" \
        "selp.b32 %0, 1, 0, p;\n\t}" : "=r"(_d) : "r"(_m), "r"(_p) : "memory"); \
    if (!_d) {                                                                \
        asm volatile("{\n\t.reg .pred P1;\n\t"                                \
            "WL_%=:\n\t"                                                      \
            "mbarrier.try_wait.parity.acquire.cta.shared::cta.b64 P1, [%0], %1, 0x989680;\n\t" \
            "@P1 bra.uni WD_%=;\n\t"                                          \
            "bra.uni WL_%=;\n\t"                                              \
            "WD_%=:\n\t}" :: "r"(_m), "r"(_p) : "memory");                    \
    }                                                                         \
} while (0)

#define TC_COMMIT(a) \
    asm volatile("tcgen05.commit.cta_group::1.mbarrier::arrive::one.shared::cluster.b64 [%0];" \
                 :: "r"(a) : "memory")

#define TMA2D(smem, map, cx, cy, mbar)                                        \
    asm volatile(                                                             \
        "cp.async.bulk.tensor.2d.shared::cta.global.tile.mbarrier::complete_tx::bytes " \
        "[%0], [%1, {%2, %3}], [%4];"                                         \
        :: "r"(smem), "l"(map), "r"(cx), "r"(cy), "r"(mbar) : "memory")

#define LDTM_X32(r, addr)                                                     \
    asm volatile("tcgen05.ld.sync.aligned.32x32b.x32.b32 "                    \
        "{%0, %1, %2, %3, %4, %5, %6, %7, "                                   \
        " %8, %9, %10, %11, %12, %13, %14, %15, "                             \
        " %16, %17, %18, %19, %20, %21, %22, %23, "                           \
        " %24, %25, %26, %27, %28, %29, %30, %31}, [%32];"                    \
        : "=r"((r)[0]),  "=r"((r)[1]),  "=r"((r)[2]),  "=r"((r)[3]),          \
          "=r"((r)[4]),  "=r"((r)[5]),  "=r"((r)[6]),  "=r"((r)[7]),          \
          "=r"((r)[8]),  "=r"((r)[9]),  "=r"((r)[10]), "=r"((r)[11]),         \
          "=r"((r)[12]), "=r"((r)[13]), "=r"((r)[14]), "=r"((r)[15]),         \
          "=r"((r)[16]), "=r"((r)[17]), "=r"((r)[18]), "=r"((r)[19]),         \
          "=r"((r)[20]), "=r"((r)[21]), "=r"((r)[22]), "=r"((r)[23]),         \
          "=r"((r)[24]), "=r"((r)[25]), "=r"((r)[26]), "=r"((r)[27]),         \
          "=r"((r)[28]), "=r"((r)[29]), "=r"((r)[30]), "=r"((r)[31])          \
        : "r"(addr))
#endif  // TC_OK

__global__ __launch_bounds__(128, 1)
void gemm_kernel(const float* __restrict__ X, const float* __restrict__ W,
                 const float* __restrict__ Bias, float* __restrict__ Y,
                 const __grid_constant__ CUtensorMap tm_xh,
                 const __grid_constant__ CUtensorMap tm_xl,
                 const __grid_constant__ CUtensorMap tm_wh,
                 const __grid_constant__ CUtensorMap tm_wl) {
    extern __shared__ char dsm[];
    const int tid = threadIdx.x;
    const int n0 = blockIdx.x * 32;
    const int m0 = blockIdx.y * 128;

#if TC_OK
    const uint32_t raw = s2u(dsm);
    const uint32_t base = (raw + 1023u) & ~1023u;

    const int wid = tid >> 5;
    const int lid = tid & 31;

    if (wid == 0)
        asm volatile(
            "tcgen05.alloc.cta_group::1.sync.aligned.shared::cta.b32 [%0], %1;"
            :: "r"(base), "r"(64u) : "memory");
    if (tid == 0) {
#pragma unroll
        for (int s = 0; s < 4; s++) {
            MBAR_INIT(base + 8 + 8 * s);    // full[s]
            MBAR_INIT(base + 48 + 8 * s);   // empty[s]
        }
    }
    asm volatile("fence.proxy.async.shared::cta;" ::: "memory");
    __syncthreads();
    uint32_t tmem;
    asm("ld.shared.b32 %0, [%1];" : "=r"(tmem) : "r"(base));

    // ---------------- producer: warp 1, lane 0 ---------------------------
    if (tid == 32) {
#pragma unroll
        for (int c = 0; c < 8; c++) {
            const int s = c & 3;
            const uint32_t full = base + 8 + 8 * s;
            if (c >= 4) MBAR_WAITP(base + 48 + 8 * s, 0);
            MBAR_EXPECT_TX(full, CHUNK_BYTES);
            const uint32_t st = base + STAGE0 + s * STAGE_STRIDE;
            const int k = c * 64;
            TMA2D(st,          (const void*)&tm_xh, k, m0, full);
            TMA2D(st + 16384,  (const void*)&tm_xl, k, m0, full);
            TMA2D(st + 32768,  (const void*)&tm_wh, k, n0, full);
            TMA2D(st + 36864,  (const void*)&tm_wl, k, n0, full);
        }
    }

    // ---------------- consumer: warp 0, lane 0 ---------------------------
    if (tid == 0) {
#pragma unroll
        for (int c = 0; c < 8; c++) {
            const int s = c & 3;
            MBAR_WAITP(base + 8 + 8 * s, c >> 2);
            const uint32_t st = base + STAGE0 + s * STAGE_STRIDE;
            const unsigned long long ah = MK_DESC(st);
            const unsigned long long al = MK_DESC(st + 16384);
            const unsigned long long bh = MK_DESC(st + 32768);
            const unsigned long long bl = MK_DESC(st + 36864);
#pragma unroll
            for (int ks = 0; ks < 4; ks++) {
                mma_f16_ss(tmem, ah + 2 * ks, bh + 2 * ks, IDESC,
                           (c == 0 && ks == 0) ? 0u : 1u);
                mma_f16_ss(tmem, ah + 2 * ks, bl + 2 * ks, IDESC, 1u);
                mma_f16_ss(tmem, al + 2 * ks, bh + 2 * ks, IDESC, 1u);
            }
            TC_COMMIT(base + 48 + 8 * s);
        }
        // commit(7) is the 2nd arrival on empty[3] -> parity 1; MMAs execute
        // in dispatch order, so this covers all accumulation.
        MBAR_WAITP(base + 48 + 8 * 3, 1);
    }

    __syncthreads();
    asm volatile("tcgen05.fence::after_thread_sync;" ::: "memory");

    {
        uint32_t d0[32];
        LDTM_X32(d0, tmem);
        asm volatile("tcgen05.wait::ld.sync.aligned;" ::: "memory");

        float* yr = Y + (m0 + wid * 32 + lid) * ND + n0;
        const float4* bias4 = (const float4*)(Bias + n0);
#pragma unroll
        for (int g = 0; g < 8; g++) {
            float4 bb = bias4[g];
            float4 r;
            r.x = __uint_as_float(d0[4 * g + 0]) + bb.x;
            r.y = __uint_as_float(d0[4 * g + 1]) + bb.y;
            r.z = __uint_as_float(d0[4 * g + 2]) + bb.z;
            r.w = __uint_as_float(d0[4 * g + 3]) + bb.w;
            *(float4*)(yr + 4 * g) = r;
        }
    }

    __syncthreads();
    if (wid == 0) {
        asm volatile("tcgen05.relinquish_alloc_permit.cta_group::1.sync.aligned;");
        asm volatile("tcgen05.dealloc.cta_group::1.sync.aligned.b32 %0, %1;"
                     :: "r"(tmem), "r"(64u));
    }
#else
    // Generic-target fallback body (compiles everywhere; never runs).
    __shared__ float ws[64][32];
    float acc[32];
#pragma unroll
    for (int j = 0; j < 32; j++) acc[j] = 0.f;
    const int m = m0 + tid;
    for (int kb = 0; kb < KD; kb += 64) {
        __syncthreads();
        for (int u = tid; u < 64 * 8; u += 128) {
            const int kr = u >> 3, nq = u & 7;
            *(float4*)&ws[kr][4 * nq] =
                *(const float4*)(W + (kb + kr) * ND + n0 + 4 * nq);
        }
        __syncthreads();
        for (int k = 0; k < 64; k++) {
            float a = X[m * KD + kb + k];
#pragma unroll
            for (int j = 0; j < 32; j++) acc[j] += a * ws[k][j];
        }
    }
    for (int j = 0; j < 32; j++) Y[m * ND + n0 + j] = acc[j] + Bias[n0 + j];
#endif
}

// Host-selected fallback if tensor-map encoding is unavailable.
__global__ __launch_bounds__(512)
void fallback_gemm(const float* __restrict__ X, const float* __restrict__ W,
                   const float* __restrict__ Bias, float* __restrict__ Y) {
    __shared__ float xs[64 * 128];
    __shared__ float ws[64 * 32];
    const int tid = threadIdx.x;
    const int n0 = blockIdx.x * 32;
    const int m0 = blockIdx.y * 128;
    const int mq = tid >> 3;
    const int nq = tid & 7;
    float acc[2][4];
#pragma unroll
    for (int i = 0; i < 2; i++)
#pragma unroll
        for (int j = 0; j < 4; j++) acc[i][j] = 0.f;

    for (int kb = 0; kb < KD; kb += 64) {
        __syncthreads();
#pragma unroll
        for (int j = 0; j < 4; j++) {
            const int u = j * 512 + tid;
            const int row = u >> 4, kq4 = u & 15;
            float4 v = *(const float4*)(X + (m0 + row) * KD + kb + 4 * kq4);
            xs[(4 * kq4 + 0) * 128 + row] = v.x;
            xs[(4 * kq4 + 1) * 128 + row] = v.y;
            xs[(4 * kq4 + 2) * 128 + row] = v.z;
            xs[(4 * kq4 + 3) * 128 + row] = v.w;
        }
        {
            const int row = tid >> 3, nq4 = tid & 7;
            *(float4*)&ws[row * 32 + 4 * nq4] =
                *(const float4*)(W + (kb + row) * ND + n0 + 4 * nq4);
        }
        __syncthreads();
#pragma unroll 8
        for (int k = 0; k < 64; k++) {
            float a0 = xs[k * 128 + mq];
            float a1 = xs[k * 128 + mq + 64];
            float4 b = *(float4*)&ws[k * 32 + 4 * nq];
            acc[0][0] += a0 * b.x; acc[0][1] += a0 * b.y;
            acc[0][2] += a0 * b.z; acc[0][3] += a0 * b.w;
            acc[1][0] += a1 * b.x; acc[1][1] += a1 * b.y;
            acc[1][2] += a1 * b.z; acc[1][3] += a1 * b.w;
        }
    }
    const float4 bb = *(const float4*)(Bias + n0 + 4 * nq);
#pragma unroll
    for (int i = 0; i < 2; i++) {
        float4 r;
        r.x = acc[i][0] + bb.x;
        r.y = acc[i][1] + bb.y;
        r.z = acc[i][2] + bb.z;
        r.w = acc[i][3] + bb.w;
        *(float4*)(Y + (m0 + mq + 64 * i) * ND + n0 + 4 * nq) = r;
    }
}

// ---------------------------------------------------------------------------
// Host
// ---------------------------------------------------------------------------
typedef CUresult (CUDAAPI* tme_fn_t)(
    CUtensorMap*, CUtensorMapDataType, cuuint32_t, void*, const cuuint64_t*,
    const cuuint64_t*, const cuuint32_t*, const cuuint32_t*,
    CUtensorMapInterleave, CUtensorMapSwizzle, CUtensorMapL2promotion,
    CUtensorMapFloatOOBfill);

extern "C" void kernel_launch(void* const* d_in, const int* in_sizes, int n_in,
                              void* d_out, int out_size) {
    const float* x = (const float*)d_in[0];  // [512, 512]
    const float* w = (const float*)d_in[1];  // [512, 512]
    const float* b = (const float*)d_in[2];  // [512]
    float* y = (float*)d_out;                // [512, 512]

    cudaFuncSetAttribute(gemm_kernel,
                         cudaFuncAttributeMaxDynamicSharedMemorySize, SMEM_DYN);

    void *pxh = nullptr, *pxl = nullptr, *pwh = nullptr, *pwl = nullptr;
    cudaGetSymbolAddress(&pxh, gXH);
    cudaGetSymbolAddress(&pxl, gXL);
    cudaGetSymbolAddress(&pwh, gWTH);
    cudaGetSymbolAddress(&pwl, gWTL);

    tme_fn_t enc = nullptr;
    cudaDriverEntryPointQueryResult qr;
    cudaGetDriverEntryPointByVersion("cuTensorMapEncodeTiled", (void**)&enc,
                                     12000, cudaEnableDefault, &qr);

    bool ok = (enc != nullptr) && pxh && pxl && pwh && pwl;
    CUtensorMap tmxh, tmxl, tmwh, tmwl;
    if (ok) {
        cuuint64_t dims[2] = {512, 512};       // {k, rows}
        cuuint64_t strides[1] = {1024};        // row stride bytes (512 bf16)
        cuuint32_t boxA[2] = {64, 128};        // {k, m}
        cuuint32_t boxW[2] = {64, 32};         // {k, n}
        cuuint32_t es[2] = {1, 1};
        ok = ok && enc(&tmxh, CU_TENSOR_MAP_DATA_TYPE_BFLOAT16, 2, pxh, dims,
                       strides, boxA, es, CU_TENSOR_MAP_INTERLEAVE_NONE,
                       CU_TENSOR_MAP_SWIZZLE_128B,
                       CU_TENSOR_MAP_L2_PROMOTION_L2_128B,
                       CU_TENSOR_MAP_FLOAT_OOB_FILL_NONE) == CUDA_SUCCESS;
        ok = ok && enc(&tmxl, CU_TENSOR_MAP_DATA_TYPE_BFLOAT16, 2, pxl, dims,
                       strides, boxA, es, CU_TENSOR_MAP_INTERLEAVE_NONE,
                       CU_TENSOR_MAP_SWIZZLE_128B,
                       CU_TENSOR_MAP_L2_PROMOTION_L2_128B,
                       CU_TENSOR_MAP_FLOAT_OOB_FILL_NONE) == CUDA_SUCCESS;
        ok = ok && enc(&tmwh, CU_TENSOR_MAP_DATA_TYPE_BFLOAT16, 2, pwh, dims,
                       strides, boxW, es, CU_TENSOR_MAP_INTERLEAVE_NONE,
                       CU_TENSOR_MAP_SWIZZLE_128B,
                       CU_TENSOR_MAP_L2_PROMOTION_L2_128B,
                       CU_TENSOR_MAP_FLOAT_OOB_FILL_NONE) == CUDA_SUCCESS;
        ok = ok && enc(&tmwl, CU_TENSOR_MAP_DATA_TYPE_BFLOAT16, 2, pwl, dims,
                       strides, boxW, es, CU_TENSOR_MAP_INTERLEAVE_NONE,
                       CU_TENSOR_MAP_SWIZZLE_128B,
                       CU_TENSOR_MAP_L2_PROMOTION_L2_128B,
                       CU_TENSOR_MAP_FLOAT_OOB_FILL_NONE) == CUDA_SUCCESS;
    }

    dim3 grid(ND / 32, MD / 128);  // (16, 4) = 64 CTAs
    if (ok) {
        convert_kernel<<<128, 256>>>(x, w);
        gemm_kernel<<<grid, 128, SMEM_DYN>>>(x, w, b, y, tmxh, tmxl, tmwh,
                                             tmwl);
    } else {
        fallback_gemm<<<grid, 512>>>(x, w, b, y);
    }
}

// round 9
// speedup vs baseline: 1.0025x; 1.0025x over previous
#include <cuda_runtime.h>
#include <cuda.h>
#include <cuda_bf16.h>
#include <cstdint>

// ---------------------------------------------------------------------------
// MemristiveLinear == y = x @ w + b (512^3 fp32), tcgen05 bf16 split:
//   x = xh+xl, w = wh+wl;  y ~= xh@wh + xh@wl + xl@wh  (+b)
//
// R9: same warp-specialized TMA pipeline as R8, with the latency round-trips
//     halved: 4 K-chunks of 128 (2-stage ring, 80KB stages; chunk = two
//     side-by-side TMA box{64,rows} loads, second k-half at +1024/+256 desc
//     units -- the R7-validated blocked-atom offsets), plus
//     prefetch.tensormap to kill cold descriptor fetches.
// tcgen05 asm guarded for the arch-specific pass; generic compute_103 pass
// compiles a correct fp32 fallback (never runs; sm_103a cubin preferred).
// ---------------------------------------------------------------------------

#if defined(__CUDA_ARCH_FEAT_SM103_ALL) || defined(__CUDA_ARCH_FEAT_SM100_ALL) || \
    defined(__CUDA_ARCH_FEAT_SM101_ALL) || defined(__CUDA_ARCH_SPECIFIC__) ||     \
    defined(__CUDA_ARCH_FAMILY_SPECIFIC__)
#define TC_OK 1
#else
#define TC_OK 0
#endif

#define MD 512
#define ND 512
#define KD 512

// bf16 scratch, stored as uint4 (8 bf16 each) for vector access.
__device__ uint4 gXH[MD * KD / 8];
__device__ uint4 gXL[MD * KD / 8];
__device__ uint4 gWTH[ND * KD / 8];
__device__ uint4 gWTL[ND * KD / 8];

// ---------------------------------------------------------------------------
// Convert kernel (validated R5/R8)
// ---------------------------------------------------------------------------
__device__ __forceinline__ void split_pair(float a, float b,
                                           unsigned& hp, unsigned& lp) {
    unsigned uha = __bfloat16_as_ushort(__float2bfloat16_rn(a));
    unsigned uhb = __bfloat16_as_ushort(__float2bfloat16_rn(b));
    float ra = a - __uint_as_float(uha << 16);
    float rb = b - __uint_as_float(uhb << 16);
    unsigned ula = __bfloat16_as_ushort(__float2bfloat16_rn(ra));
    unsigned ulb = __bfloat16_as_ushort(__float2bfloat16_rn(rb));
    hp = uha | (uhb << 16);
    lp = ula | (ulb << 16);
}

__global__ __launch_bounds__(256)
void convert_kernel(const float* __restrict__ X, const float* __restrict__ W) {
    __shared__ float sm[64][65];
    const int t = threadIdx.x;
    const int b = blockIdx.x;

    if (b < 64) {
        const float4* X4 = (const float4*)X;
        uint2* XH2 = (uint2*)gXH;
        uint2* XL2 = (uint2*)gXL;
#pragma unroll
        for (int j = 0; j < 4; j++) {
            const int f4 = b * 1024 + j * 256 + t;
            float4 v = X4[f4];
            unsigned h01, l01, h23, l23;
            split_pair(v.x, v.y, h01, l01);
            split_pair(v.z, v.w, h23, l23);
            XH2[f4] = make_uint2(h01, h23);
            XL2[f4] = make_uint2(l01, l23);
        }
    } else {
        const int bb = b - 64;
        const int tk = bb >> 3, tn = bb & 7;
        const int r = t >> 2, q4 = t & 3;
        const float* wrow = W + (tk * 64 + r) * ND + tn * 64;
#pragma unroll
        for (int j = 0; j < 4; j++) {
            float4 v = *(const float4*)(wrow + (q4 * 4 + j) * 4);
            sm[r][(q4 * 4 + j) * 4 + 0] = v.x;
            sm[r][(q4 * 4 + j) * 4 + 1] = v.y;
            sm[r][(q4 * 4 + j) * 4 + 2] = v.z;
            sm[r][(q4 * 4 + j) * 4 + 3] = v.w;
        }
        __syncthreads();
        const int c = t >> 2, qr = t & 3;
        uint2* WH2 = (uint2*)gWTH;
        uint2* WL2 = (uint2*)gWTL;
        const int outbase = ((tn * 64 + c) * KD + tk * 64 + qr * 16) / 4;
#pragma unroll
        for (int g = 0; g < 4; g++) {
            float v0 = sm[qr * 16 + 4 * g + 0][c];
            float v1 = sm[qr * 16 + 4 * g + 1][c];
            float v2 = sm[qr * 16 + 4 * g + 2][c];
            float v3 = sm[qr * 16 + 4 * g + 3][c];
            unsigned h01, l01, h23, l23;
            split_pair(v0, v1, h01, l01);
            split_pair(v2, v3, h23, l23);
            WH2[outbase + g] = make_uint2(h01, h23);
            WL2[outbase + g] = make_uint2(l01, l23);
        }
    }
}

// ---------------------------------------------------------------------------
// GEMM kernel
// ---------------------------------------------------------------------------
#define DESC_BASE 0x4000404000010000ull
#define MK_DESC(addr) (DESC_BASE | (((unsigned long long)((addr) >> 4)) & 0x3FFF))
// kind::f16 idesc: F32 acc, BF16 a/b, M=128, N=32 (validated R5-R8)
#define IDESC ((1u << 4) | (1u << 7) | (1u << 10) | (4u << 17) | (8u << 24))

// smem map (relative to 1024-aligned base):
//   0: tmem ptr | 8,16: full[2] | 24,32: empty[2]
//   stage s at 1024 + s*81920:
//     Ah[0] 16K | Ah[1] 16K | Al[0] 16K | Al[1] 16K |
//     Wh[0] 4K | Wh[1] 4K | Wl[0] 4K | Wl[1] 4K        (80 KB)
#define STAGE0 1024
#define STAGE_STRIDE 81920
#define CHUNK_BYTES 81920
#define SMEM_DYN (STAGE0 + 2 * STAGE_STRIDE + 1024)  // 165888

__device__ __forceinline__ uint32_t s2u(const void* p) {
    uint32_t a;
    asm("{ .reg .u64 t; cvta.to.shared.u64 t, %1; cvt.u32.u64 %0, t; }"
        : "=r"(a) : "l"(p));
    return a;
}

#if TC_OK
__device__ __forceinline__ void mma_f16_ss(uint32_t d, unsigned long long ad,
                                           unsigned long long bd,
                                           uint32_t idesc, uint32_t en) {
    asm volatile(
        "{\n\t.reg .pred p;\n\tsetp.ne.u32 p, %5, 0;\n\t"
        "tcgen05.mma.cta_group::1.kind::f16 [%0], %1, %2, %3, {%4, %4, %4, %4}, p;\n\t}"
        :: "r"(d), "l"(ad), "l"(bd), "r"(idesc), "r"(0u), "r"(en)
        : "memory");
}

#define MBAR_INIT(a) \
    asm volatile("mbarrier.init.shared.b64 [%0], %1;" :: "r"(a), "r"(1u) : "memory")

#define MBAR_EXPECT_TX(a, n) \
    asm volatile("mbarrier.arrive.expect_tx.shared.b64 _, [%0], %1;" \
                 :: "r"(a), "r"(n) : "memory")

#define MBAR_WAITP(a, ph) do {                                                \
    unsigned _m = (a), _p = (ph), _d;                                         \
    asm volatile("{\n\t.reg .pred p;\n\t"                                     \
        "mbarrier.try_wait.parity.acquire.cta.shared::cta.b64 p, [%1], %2;\n\t" \
        "selp.b32 %0, 1, 0, p;\n\t}" : "=r"(_d) : "r"(_m), "r"(_p) : "memory"); \
    if (!_d) {                                                                \
        asm volatile("{\n\t.reg .pred P1;\n\t"                                \
            "WL_%=:\n\t"                                                      \
            "mbarrier.try_wait.parity.acquire.cta.shared::cta.b64 P1, [%0], %1, 0x989680;\n\t" \
            "@P1 bra.uni WD_%=;\n\t"                                          \
            "bra.uni WL_%=;\n\t"                                              \
            "WD_%=:\n\t}" :: "r"(_m), "r"(_p) : "memory");                    \
    }                                                                         \
} while (0)

#define TC_COMMIT(a) \
    asm volatile("tcgen05.commit.cta_group::1.mbarrier::arrive::one.shared::cluster.b64 [%0];" \
                 :: "r"(a) : "memory")

#define TMA2D(smem, map, cx, cy, mbar)                                        \
    asm volatile(                                                             \
        "cp.async.bulk.tensor.2d.shared::cta.global.tile.mbarrier::complete_tx::bytes " \
        "[%0], [%1, {%2, %3}], [%4];"                                         \
        :: "r"(smem), "l"(map), "r"(cx), "r"(cy), "r"(mbar) : "memory")

#define TMA_PREFETCH(map) \
    asm volatile("prefetch.tensormap [%0];" :: "l"(map))

#define LDTM_X32(r, addr)                                                     \
    asm volatile("tcgen05.ld.sync.aligned.32x32b.x32.b32 "                    \
        "{%0, %1, %2, %3, %4, %5, %6, %7, "                                   \
        " %8, %9, %10, %11, %12, %13, %14, %15, "                             \
        " %16, %17, %18, %19, %20, %21, %22, %23, "                           \
        " %24, %25, %26, %27, %28, %29, %30, %31}, [%32];"                    \
        : "=r"((r)[0]),  "=r"((r)[1]),  "=r"((r)[2]),  "=r"((r)[3]),          \
          "=r"((r)[4]),  "=r"((r)[5]),  "=r"((r)[6]),  "=r"((r)[7]),          \
          "=r"((r)[8]),  "=r"((r)[9]),  "=r"((r)[10]), "=r"((r)[11]),         \
          "=r"((r)[12]), "=r"((r)[13]), "=r"((r)[14]), "=r"((r)[15]),         \
          "=r"((r)[16]), "=r"((r)[17]), "=r"((r)[18]), "=r"((r)[19]),         \
          "=r"((r)[20]), "=r"((r)[21]), "=r"((r)[22]), "=r"((r)[23]),         \
          "=r"((r)[24]), "=r"((r)[25]), "=r"((r)[26]), "=r"((r)[27]),         \
          "=r"((r)[28]), "=r"((r)[29]), "=r"((r)[30]), "=r"((r)[31])          \
        : "r"(addr))
#endif  // TC_OK

__global__ __launch_bounds__(128, 1)
void gemm_kernel(const float* __restrict__ X, const float* __restrict__ W,
                 const float* __restrict__ Bias, float* __restrict__ Y,
                 const __grid_constant__ CUtensorMap tm_xh,
                 const __grid_constant__ CUtensorMap tm_xl,
                 const __grid_constant__ CUtensorMap tm_wh,
                 const __grid_constant__ CUtensorMap tm_wl) {
    extern __shared__ char dsm[];
    const int tid = threadIdx.x;
    const int n0 = blockIdx.x * 32;
    const int m0 = blockIdx.y * 128;

#if TC_OK
    const uint32_t raw = s2u(dsm);
    const uint32_t base = (raw + 1023u) & ~1023u;

    const int wid = tid >> 5;
    const int lid = tid & 31;

    if (tid >= 32 && tid < 36) {
        // Prefetch all 4 tensormaps early (one per thread).
        const void* maps[4] = {&tm_xh, &tm_xl, &tm_wh, &tm_wl};
        TMA_PREFETCH(maps[tid - 32]);
    }

    if (wid == 0)
        asm volatile(
            "tcgen05.alloc.cta_group::1.sync.aligned.shared::cta.b32 [%0], %1;"
            :: "r"(base), "r"(64u) : "memory");
    if (tid == 0) {
        MBAR_INIT(base + 8);    // full[0]
        MBAR_INIT(base + 16);   // full[1]
        MBAR_INIT(base + 24);   // empty[0]
        MBAR_INIT(base + 32);   // empty[1]
    }
    asm volatile("fence.proxy.async.shared::cta;" ::: "memory");
    __syncthreads();
    uint32_t tmem;
    asm("ld.shared.b32 %0, [%1];" : "=r"(tmem) : "r"(base));

    // ---------------- producer: warp 1, lane 0 ---------------------------
    if (tid == 32) {
#pragma unroll
        for (int c = 0; c < 4; c++) {
            const int s = c & 1;
            const uint32_t full = base + 8 + 8 * s;
            if (c >= 2) MBAR_WAITP(base + 24 + 8 * s, 0);
            MBAR_EXPECT_TX(full, CHUNK_BYTES);
            const uint32_t st = base + STAGE0 + s * STAGE_STRIDE;
            const int k = c * 128;
            TMA2D(st +     0, (const void*)&tm_xh, k,      m0, full);
            TMA2D(st + 16384, (const void*)&tm_xh, k + 64, m0, full);
            TMA2D(st + 32768, (const void*)&tm_xl, k,      m0, full);
            TMA2D(st + 49152, (const void*)&tm_xl, k + 64, m0, full);
            TMA2D(st + 65536, (const void*)&tm_wh, k,      n0, full);
            TMA2D(st + 69632, (const void*)&tm_wh, k + 64, n0, full);
            TMA2D(st + 73728, (const void*)&tm_wl, k,      n0, full);
            TMA2D(st + 77824, (const void*)&tm_wl, k + 64, n0, full);
        }
    }

    // ---------------- consumer: warp 0, lane 0 ---------------------------
    if (tid == 0) {
#pragma unroll
        for (int c = 0; c < 4; c++) {
            const int s = c & 1;
            MBAR_WAITP(base + 8 + 8 * s, c >> 1);
            const uint32_t st = base + STAGE0 + s * STAGE_STRIDE;
            const unsigned long long ah = MK_DESC(st);
            const unsigned long long al = MK_DESC(st + 32768);
            const unsigned long long bh = MK_DESC(st + 65536);
            const unsigned long long bl = MK_DESC(st + 73728);
#pragma unroll
            for (int ks = 0; ks < 8; ks++) {
                // Blocked-atom desc offsets (validated in R7/R8):
                const int ao = (ks < 4) ? 2 * ks : 1024 + 2 * (ks - 4);
                const int bo = (ks < 4) ? 2 * ks : 256 + 2 * (ks - 4);
                mma_f16_ss(tmem, ah + ao, bh + bo, IDESC,
                           (c == 0 && ks == 0) ? 0u : 1u);
                mma_f16_ss(tmem, ah + ao, bl + bo, IDESC, 1u);
                mma_f16_ss(tmem, al + ao, bh + bo, IDESC, 1u);
            }
            TC_COMMIT(base + 24 + 8 * s);
        }
        // empty[1]'s second arrival (chunk 3's commit) covers all MMAs.
        MBAR_WAITP(base + 24 + 8 * 1, 1);
    }

    __syncthreads();
    asm volatile("tcgen05.fence::after_thread_sync;" ::: "memory");

    {
        uint32_t d0[32];
        LDTM_X32(d0, tmem);
        asm volatile("tcgen05.wait::ld.sync.aligned;" ::: "memory");

        float* yr = Y + (m0 + wid * 32 + lid) * ND + n0;
        const float4* bias4 = (const float4*)(Bias + n0);
#pragma unroll
        for (int g = 0; g < 8; g++) {
            float4 bb = bias4[g];
            float4 r;
            r.x = __uint_as_float(d0[4 * g + 0]) + bb.x;
            r.y = __uint_as_float(d0[4 * g + 1]) + bb.y;
            r.z = __uint_as_float(d0[4 * g + 2]) + bb.z;
            r.w = __uint_as_float(d0[4 * g + 3]) + bb.w;
            *(float4*)(yr + 4 * g) = r;
        }
    }

    __syncthreads();
    if (wid == 0) {
        asm volatile("tcgen05.relinquish_alloc_permit.cta_group::1.sync.aligned;");
        asm volatile("tcgen05.dealloc.cta_group::1.sync.aligned.b32 %0, %1;"
                     :: "r"(tmem), "r"(64u));
    }
#else
    // Generic-target fallback body (compiles everywhere; never runs).
    __shared__ float ws[64][32];
    float acc[32];
#pragma unroll
    for (int j = 0; j < 32; j++) acc[j] = 0.f;
    const int m = m0 + tid;
    for (int kb = 0; kb < KD; kb += 64) {
        __syncthreads();
        for (int u = tid; u < 64 * 8; u += 128) {
            const int kr = u >> 3, nq = u & 7;
            *(float4*)&ws[kr][4 * nq] =
                *(const float4*)(W + (kb + kr) * ND + n0 + 4 * nq);
        }
        __syncthreads();
        for (int k = 0; k < 64; k++) {
            float a = X[m * KD + kb + k];
#pragma unroll
            for (int j = 0; j < 32; j++) acc[j] += a * ws[k][j];
        }
    }
    for (int j = 0; j < 32; j++) Y[m * ND + n0 + j] = acc[j] + Bias[n0 + j];
#endif
}

// Host-selected fallback if tensor-map encoding is unavailable.
__global__ __launch_bounds__(512)
void fallback_gemm(const float* __restrict__ X, const float* __restrict__ W,
                   const float* __restrict__ Bias, float* __restrict__ Y) {
    __shared__ float xs[64 * 128];
    __shared__ float ws[64 * 32];
    const int tid = threadIdx.x;
    const int n0 = blockIdx.x * 32;
    const int m0 = blockIdx.y * 128;
    const int mq = tid >> 3;
    const int nq = tid & 7;
    float acc[2][4];
#pragma unroll
    for (int i = 0; i < 2; i++)
#pragma unroll
        for (int j = 0; j < 4; j++) acc[i][j] = 0.f;

    for (int kb = 0; kb < KD; kb += 64) {
        __syncthreads();
#pragma unroll
        for (int j = 0; j < 4; j++) {
            const int u = j * 512 + tid;
            const int row = u >> 4, kq4 = u & 15;
            float4 v = *(const float4*)(X + (m0 + row) * KD + kb + 4 * kq4);
            xs[(4 * kq4 + 0) * 128 + row] = v.x;
            xs[(4 * kq4 + 1) * 128 + row] = v.y;
            xs[(4 * kq4 + 2) * 128 + row] = v.z;
            xs[(4 * kq4 + 3) * 128 + row] = v.w;
        }
        {
            const int row = tid >> 3, nq4 = tid & 7;
            *(float4*)&ws[row * 32 + 4 * nq4] =
                *(const float4*)(W + (kb + row) * ND + n0 + 4 * nq4);
        }
        __syncthreads();
#pragma unroll 8
        for (int k = 0; k < 64; k++) {
            float a0 = xs[k * 128 + mq];
            float a1 = xs[k * 128 + mq + 64];
            float4 b = *(float4*)&ws[k * 32 + 4 * nq];
            acc[0][0] += a0 * b.x; acc[0][1] += a0 * b.y;
            acc[0][2] += a0 * b.z; acc[0][3] += a0 * b.w;
            acc[1][0] += a1 * b.x; acc[1][1] += a1 * b.y;
            acc[1][2] += a1 * b.z; acc[1][3] += a1 * b.w;
        }
    }
    const float4 bb = *(const float4*)(Bias + n0 + 4 * nq);
#pragma unroll
    for (int i = 0; i < 2; i++) {
        float4 r;
        r.x = acc[i][0] + bb.x;
        r.y = acc[i][1] + bb.y;
        r.z = acc[i][2] + bb.z;
        r.w = acc[i][3] + bb.w;
        *(float4*)(Y + (m0 + mq + 64 * i) * ND + n0 + 4 * nq) = r;
    }
}

// ---------------------------------------------------------------------------
// Host
// ---------------------------------------------------------------------------
typedef CUresult (CUDAAPI* tme_fn_t)(
    CUtensorMap*, CUtensorMapDataType, cuuint32_t, void*, const cuuint64_t*,
    const cuuint64_t*, const cuuint32_t*, const cuuint32_t*,
    CUtensorMapInterleave, CUtensorMapSwizzle, CUtensorMapL2promotion,
    CUtensorMapFloatOOBfill);

extern "C" void kernel_launch(void* const* d_in, const int* in_sizes, int n_in,
                              void* d_out, int out_size) {
    const float* x = (const float*)d_in[0];  // [512, 512]
    const float* w = (const float*)d_in[1];  // [512, 512]
    const float* b = (const float*)d_in[2];  // [512]
    float* y = (float*)d_out;                // [512, 512]

    cudaFuncSetAttribute(gemm_kernel,
                         cudaFuncAttributeMaxDynamicSharedMemorySize, SMEM_DYN);

    void *pxh = nullptr, *pxl = nullptr, *pwh = nullptr, *pwl = nullptr;
    cudaGetSymbolAddress(&pxh, gXH);
    cudaGetSymbolAddress(&pxl, gXL);
    cudaGetSymbolAddress(&pwh, gWTH);
    cudaGetSymbolAddress(&pwl, gWTL);

    tme_fn_t enc = nullptr;
    cudaDriverEntryPointQueryResult qr;
    cudaGetDriverEntryPointByVersion("cuTensorMapEncodeTiled", (void**)&enc,
                                     12000, cudaEnableDefault, &qr);

    bool ok = (enc != nullptr) && pxh && pxl && pwh && pwl;
    CUtensorMap tmxh, tmxl, tmwh, tmwl;
    if (ok) {
        cuuint64_t dims[2] = {512, 512};       // {k, rows}
        cuuint64_t strides[1] = {1024};        // row stride bytes (512 bf16)
        cuuint32_t boxA[2] = {64, 128};        // {k, m}
        cuuint32_t boxW[2] = {64, 32};         // {k, n}
        cuuint32_t es[2] = {1, 1};
        ok = ok && enc(&tmxh, CU_TENSOR_MAP_DATA_TYPE_BFLOAT16, 2, pxh, dims,
                       strides, boxA, es, CU_TENSOR_MAP_INTERLEAVE_NONE,
                       CU_TENSOR_MAP_SWIZZLE_128B,
                       CU_TENSOR_MAP_L2_PROMOTION_L2_128B,
                       CU_TENSOR_MAP_FLOAT_OOB_FILL_NONE) == CUDA_SUCCESS;
        ok = ok && enc(&tmxl, CU_TENSOR_MAP_DATA_TYPE_BFLOAT16, 2, pxl, dims,
                       strides, boxA, es, CU_TENSOR_MAP_INTERLEAVE_NONE,
                       CU_TENSOR_MAP_SWIZZLE_128B,
                       CU_TENSOR_MAP_L2_PROMOTION_L2_128B,
                       CU_TENSOR_MAP_FLOAT_OOB_FILL_NONE) == CUDA_SUCCESS;
        ok = ok && enc(&tmwh, CU_TENSOR_MAP_DATA_TYPE_BFLOAT16, 2, pwh, dims,
                       strides, boxW, es, CU_TENSOR_MAP_INTERLEAVE_NONE,
                       CU_TENSOR_MAP_SWIZZLE_128B,
                       CU_TENSOR_MAP_L2_PROMOTION_L2_128B,
                       CU_TENSOR_MAP_FLOAT_OOB_FILL_NONE) == CUDA_SUCCESS;
        ok = ok && enc(&tmwl, CU_TENSOR_MAP_DATA_TYPE_BFLOAT16, 2, pwl, dims,
                       strides, boxW, es, CU_TENSOR_MAP_INTERLEAVE_NONE,
                       CU_TENSOR_MAP_SWIZZLE_128B,
                       CU_TENSOR_MAP_L2_PROMOTION_L2_128B,
                       CU_TENSOR_MAP_FLOAT_OOB_FILL_NONE) == CUDA_SUCCESS;
    }

    dim3 grid(ND / 32, MD / 128);  // (16, 4) = 64 CTAs
    if (ok) {
        convert_kernel<<<128, 256>>>(x, w);
        gemm_kernel<<<grid, 128, SMEM_DYN>>>(x, w, b, y, tmxh, tmxl, tmwh,
                                             tmwl);
    } else {
        fallback_gemm<<<grid, 512>>>(x, w, b, y);
    }
}